// round 11
// baseline (speedup 1.0000x reference)
#include <cuda_runtime.h>
#include <cuda_bf16.h>
#include <cstdint>

#define NB 128
#define CD 256
#define KK 64
#define PT 1024

// ---- smem byte offsets ----
#define SM_X0   0            // x tile bf16 [256 c][136 p] (stride 272 B)
#define SM_X1   69632
#define XSTR    272
#define SM_W    139264       // W bf16 [64 k][264 c]
#define WSTR    528
#define SM_AT0  173056       // at bf16 [64 k][136 p], double buffered
#define SM_AT1  190464
#define ASTR    272
#define SM_SQ0  207872       // 128 x 9 f, double buffered
#define SM_SQ1  212480
#define SM_RED  217088       // 64 x 33 f (asum accum) / 64 x 5 f (epilogue)
#define SM_ASUM 225536
#define SM_RK   225792
#define SM_BIAS 226048
#define SM_G2   226304
#define SM_TOTAL 226312

__device__ __forceinline__ uint32_t smem_u32(const void* p) {
    uint32_t a;
    asm("{ .reg .u64 t; cvta.to.shared.u64 t, %1; cvt.u32.u64 %0, t; }" : "=r"(a) : "l"(p));
    return a;
}
__device__ __forceinline__ uint32_t bf2(float lo, float hi) {
    uint32_t r;
    asm("cvt.rn.bf16x2.f32 %0, %1, %2;" : "=r"(r) : "f"(hi), "f"(lo));
    return r;
}
__device__ __forceinline__ void ldm4t(uint32_t* r, uint32_t addr) {
    asm volatile("ldmatrix.sync.aligned.m8n8.x4.trans.shared.b16 {%0,%1,%2,%3}, [%4];"
                 : "=r"(r[0]), "=r"(r[1]), "=r"(r[2]), "=r"(r[3]) : "r"(addr));
}
__device__ __forceinline__ void ldm4(uint32_t* r, uint32_t addr) {
    asm volatile("ldmatrix.sync.aligned.m8n8.x4.shared.b16 {%0,%1,%2,%3}, [%4];"
                 : "=r"(r[0]), "=r"(r[1]), "=r"(r[2]), "=r"(r[3]) : "r"(addr));
}
__device__ __forceinline__ void mma_bf16(float* d, const uint32_t* a, uint32_t b0, uint32_t b1) {
    asm volatile("mma.sync.aligned.m16n8k16.row.col.f32.bf16.bf16.f32 "
                 "{%0,%1,%2,%3}, {%4,%5,%6,%7}, {%8,%9}, {%0,%1,%2,%3};"
                 : "+f"(d[0]), "+f"(d[1]), "+f"(d[2]), "+f"(d[3])
                 : "r"(a[0]), "r"(a[1]), "r"(a[2]), "r"(a[3]), "r"(b0), "r"(b1));
}
__device__ __forceinline__ void sts16(uint32_t addr, __nv_bfloat16 v) {
    unsigned short u = *(unsigned short*)&v;
    asm volatile("st.shared.u16 [%0], %1;" :: "r"(addr), "h"(u) : "memory");
}

__global__ __launch_bounds__(512, 1) void netvlad_mma(
    const float* __restrict__ x, const float* __restrict__ w,
    const float* __restrict__ b, const float* __restrict__ cent,
    float* __restrict__ out) {
    extern __shared__ char smem[];
    float* smf = (float*)smem;
    const uint32_t sb = smem_u32(smem);
    const int t = threadIdx.x, lane = t & 31, wp = t >> 5;
    const int la = lane & 7, grp = lane >> 3, qr = lane >> 2, qc = lane & 3;
    const int n = blockIdx.x;
    const float* xn = x + (size_t)n * CD * PT;
    const int wq = wp - 8;                   // valid for warps 8-15
    const int kg = wq & 1, cg = wq >> 1;     // GEMM2: k32 x c64 per warp

    // ---- pre-loop: warps 0-7 load W + bias + zero RED; warps 8-15 load tile 0 ----
    if (wp < 8) {
#pragma unroll
        for (int i = 0; i < 32; i++) {
            int id2 = t + (i << 8);
            int kk = id2 >> 7, c2 = id2 & 127;
            float2 v = ((const float2*)w)[id2];
            *(uint32_t*)(smem + SM_W + kk * WSTR + c2 * 4) = bf2(v.x, v.y);
        }
        if (t < KK) smf[(SM_BIAS >> 2) + t] = b[t];
        for (int i = t; i < 64 * 33; i += 256) smf[(SM_RED >> 2) + i] = 0.f;
    } else {
        const float* xp = xn + lane * 4;
        float s0 = 0.f, s1 = 0.f, s2 = 0.f, s3 = 0.f;
#pragma unroll 8
        for (int ci = 0; ci < 32; ci++) {
            int c = wq * 32 + ci;
            float4 v = *(const float4*)(xp + (size_t)c * PT);
            s0 += v.x * v.x; s1 += v.y * v.y; s2 += v.z * v.z; s3 += v.w * v.w;
            *(uint2*)(smem + SM_X0 + c * XSTR + lane * 8) =
                make_uint2(bf2(v.x, v.y), bf2(v.z, v.w));
        }
        float* sq = smf + (SM_SQ0 >> 2);
        sq[(lane * 4 + 0) * 9 + wq] = s0;
        sq[(lane * 4 + 1) * 9 + wq] = s1;
        sq[(lane * 4 + 2) * 9 + wq] = s2;
        sq[(lane * 4 + 3) * 9 + wq] = s3;
    }

    // ldmatrix offsets
    const uint32_t aG1off = (uint32_t)(la + ((grp >> 1) << 3)) * XSTR +
                            (uint32_t)(wp * 16 + ((grp & 1) << 3)) * 2;
    const uint32_t wG1 = sb + SM_W + (uint32_t)la * WSTR + (uint32_t)(grp * 8) * 2;
    const uint32_t aG2off = (uint32_t)(kg * 32 + la + ((grp & 1) << 3)) * ASTR +
                            (uint32_t)((grp >> 1) << 3) * 2;
    const uint32_t xG2off = (uint32_t)(cg * 64 + la) * XSTR + (uint32_t)(grp * 8) * 2;
    const int plo = wp * 16 + qr, phi = plo + 8;

    float agg[2][8][4];
#pragma unroll
    for (int i = 0; i < 2; i++)
#pragma unroll
        for (int j = 0; j < 8; j++)
#pragma unroll
            for (int q = 0; q < 4; q++) agg[i][j][q] = 0.f;

    __syncthreads();

    // ---- 3-stage pipeline: GEMM1(it) || GEMM2(it-1) -> load(it+1) ----
    for (int it = 0; it < 9; it++) {
        if (wp < 8) {
            if (it < 8) {
                const uint32_t aG1 = sb + ((it & 1) ? SM_X1 : SM_X0) + aG1off;
                const uint32_t atw = sb + ((it & 1) ? SM_AT1 : SM_AT0);
                const uint32_t sqb = (it & 1) ? SM_SQ1 : SM_SQ0;

                float acc[8][4];
#pragma unroll
                for (int i = 0; i < 8; i++)
#pragma unroll
                    for (int q = 0; q < 4; q++) acc[i][q] = 0.f;
#pragma unroll
                for (int cb32 = 0; cb32 < 256; cb32 += 32) {
                    uint32_t afA[4], afB[4];
                    ldm4t(afA, aG1 + (uint32_t)cb32 * XSTR);
                    ldm4t(afB, aG1 + (uint32_t)(cb32 + 16) * XSTR);
#pragma unroll
                    for (int nt = 0; nt < 8; nt++) {
                        uint32_t wf[4];
                        ldm4(wf, wG1 + (uint32_t)nt * (8 * WSTR) + (uint32_t)cb32 * 2);
                        mma_bf16(acc[nt], afA, wf[0], wf[1]);
                        mma_bf16(acc[nt], afB, wf[2], wf[3]);
                    }
                }

                // inv-norm (full per-thread sum, broadcast LDS)
                float qlo = 0.f, qhi = 0.f;
                const float* sqp = smf + (sqb >> 2);
#pragma unroll
                for (int i = 0; i < 8; i++) {
                    qlo += sqp[plo * 9 + i];
                    qhi += sqp[phi * 9 + i];
                }
                const float invlo = 1.0f / fmaxf(sqrtf(qlo), 1e-12f);
                const float invhi = 1.0f / fmaxf(sqrtf(qhi), 1e-12f);

                float mlo = -1e30f, mhi = -1e30f;
#pragma unroll
                for (int nt = 0; nt < 8; nt++) {
                    float b0 = smf[(SM_BIAS >> 2) + nt * 8 + qc * 2];
                    float b1 = smf[(SM_BIAS >> 2) + nt * 8 + qc * 2 + 1];
                    acc[nt][0] = acc[nt][0] * invlo + b0;
                    acc[nt][1] = acc[nt][1] * invlo + b1;
                    acc[nt][2] = acc[nt][2] * invhi + b0;
                    acc[nt][3] = acc[nt][3] * invhi + b1;
                    mlo = fmaxf(mlo, fmaxf(acc[nt][0], acc[nt][1]));
                    mhi = fmaxf(mhi, fmaxf(acc[nt][2], acc[nt][3]));
                }
                mlo = fmaxf(mlo, __shfl_xor_sync(0xffffffffu, mlo, 1));
                mlo = fmaxf(mlo, __shfl_xor_sync(0xffffffffu, mlo, 2));
                mhi = fmaxf(mhi, __shfl_xor_sync(0xffffffffu, mhi, 1));
                mhi = fmaxf(mhi, __shfl_xor_sync(0xffffffffu, mhi, 2));
                float slo = 0.f, shi = 0.f;
#pragma unroll
                for (int nt = 0; nt < 8; nt++) {
                    acc[nt][0] = __expf(acc[nt][0] - mlo); slo += acc[nt][0];
                    acc[nt][1] = __expf(acc[nt][1] - mlo); slo += acc[nt][1];
                    acc[nt][2] = __expf(acc[nt][2] - mhi); shi += acc[nt][2];
                    acc[nt][3] = __expf(acc[nt][3] - mhi); shi += acc[nt][3];
                }
                slo += __shfl_xor_sync(0xffffffffu, slo, 1);
                slo += __shfl_xor_sync(0xffffffffu, slo, 2);
                shi += __shfl_xor_sync(0xffffffffu, shi, 1);
                shi += __shfl_xor_sync(0xffffffffu, shi, 2);
                const float rlo = 1.0f / slo, rhi = 1.0f / shi;
                const float wlo = rlo * invlo, whi = rhi * invhi;

                float asv[16];
#pragma unroll
                for (int nt = 0; nt < 8; nt++) {
                    float a0 = acc[nt][0] * rlo, a1 = acc[nt][1] * rlo;
                    float a2 = acc[nt][2] * rhi, a3 = acc[nt][3] * rhi;
                    asv[nt * 2]     = a0 + a2;
                    asv[nt * 2 + 1] = a1 + a3;
                    int k0 = nt * 8 + qc * 2;
                    uint32_t base0 = atw + (uint32_t)k0 * ASTR;
                    sts16(base0 + (uint32_t)plo * 2, __float2bfloat16(acc[nt][0] * wlo));
                    sts16(base0 + ASTR + (uint32_t)plo * 2, __float2bfloat16(acc[nt][1] * wlo));
                    sts16(base0 + (uint32_t)phi * 2, __float2bfloat16(acc[nt][2] * whi));
                    sts16(base0 + ASTR + (uint32_t)phi * 2, __float2bfloat16(acc[nt][3] * whi));
                }
#pragma unroll
                for (int j = 0; j < 16; j++)
                    asv[j] += __shfl_xor_sync(0xffffffffu, asv[j], 4);
                if ((qr & 1) == 0) {
                    int col = wp * 4 + (qr >> 1);
#pragma unroll
                    for (int nt = 0; nt < 8; nt++) {
                        int k0 = nt * 8 + qc * 2;
                        smf[(SM_RED >> 2) + k0 * 33 + col] += asv[nt * 2];
                        smf[(SM_RED >> 2) + (k0 + 1) * 33 + col] += asv[nt * 2 + 1];
                    }
                }
            }
        } else {
            if (it > 0) {
                // GEMM2(it-1): agg[k32][c64] += at @ x^T
                const uint32_t xg2 = sb + ((it & 1) ? SM_X0 : SM_X1) + xG2off;
                const uint32_t ag2 = sb + ((it & 1) ? SM_AT0 : SM_AT1) + aG2off;
#pragma unroll
                for (int q4 = 0; q4 < 4; q4++) {
                    const uint32_t pb2 = (uint32_t)(q4 * 64);
                    uint32_t bfr[8][4];
#pragma unroll
                    for (int nt = 0; nt < 8; nt++)
                        ldm4(bfr[nt], xg2 + (uint32_t)nt * (8 * XSTR) + pb2);
                    uint32_t afr[2][2][4];
#pragma unroll
                    for (int mt = 0; mt < 2; mt++) {
                        ldm4(afr[mt][0], ag2 + (uint32_t)mt * 16 * ASTR + pb2);
                        ldm4(afr[mt][1], ag2 + (uint32_t)mt * 16 * ASTR + pb2 + 32);
                    }
#pragma unroll
                    for (int mt = 0; mt < 2; mt++)
#pragma unroll
                        for (int nt = 0; nt < 8; nt++) {
                            mma_bf16(agg[mt][nt], afr[mt][0], bfr[nt][0], bfr[nt][1]);
                            mma_bf16(agg[mt][nt], afr[mt][1], bfr[nt][2], bfr[nt][3]);
                        }
                }
            }
            if (it > 0 && it < 7)
                asm volatile("bar.sync 1, 256;" ::: "memory");  // order GEMM2 reads vs loads
            if (it < 7) {
                // load tile it+1 (tiles 1..7) into the buffer GEMM2 just released
                const uint32_t xnb = (it & 1) ? SM_X0 : SM_X1;
                const uint32_t sqn = (it & 1) ? SM_SQ0 : SM_SQ1;
                const float* xp = xn + ((it + 1) << 7) + lane * 4;
                float s0 = 0.f, s1 = 0.f, s2 = 0.f, s3 = 0.f;
#pragma unroll 8
                for (int ci = 0; ci < 32; ci++) {
                    int c = wq * 32 + ci;
                    float4 v = *(const float4*)(xp + (size_t)c * PT);
                    s0 += v.x * v.x; s1 += v.y * v.y; s2 += v.z * v.z; s3 += v.w * v.w;
                    *(uint2*)(smem + xnb + c * XSTR + lane * 8) =
                        make_uint2(bf2(v.x, v.y), bf2(v.z, v.w));
                }
                float* sq = smf + (sqn >> 2);
                sq[(lane * 4 + 0) * 9 + wq] = s0;
                sq[(lane * 4 + 1) * 9 + wq] = s1;
                sq[(lane * 4 + 2) * 9 + wq] = s2;
                sq[(lane * 4 + 3) * 9 + wq] = s3;
            }
        }
        __syncthreads();
    }

    // ---- epilogue ----
    if (t < 64) {
        float s = 0.f;
#pragma unroll
        for (int i = 0; i < 32; i++) s += smf[(SM_RED >> 2) + t * 33 + i];
        smf[(SM_ASUM >> 2) + t] = s;
    }
    __syncthreads();
    if (wp >= 8) {
#pragma unroll
        for (int mt = 0; mt < 2; mt++) {
            int kA = kg * 32 + mt * 16 + qr, kB = kA + 8;
            float as0 = smf[(SM_ASUM >> 2) + kA];
            float as1 = smf[(SM_ASUM >> 2) + kB];
#pragma unroll
            for (int nt = 0; nt < 8; nt++) {
                int c0 = cg * 64 + nt * 8 + qc * 2;
                float2 ce0 = *(const float2*)(cent + kA * CD + c0);
                float2 ce1 = *(const float2*)(cent + kB * CD + c0);
                agg[mt][nt][0] -= as0 * ce0.x;
                agg[mt][nt][1] -= as0 * ce0.y;
                agg[mt][nt][2] -= as1 * ce1.x;
                agg[mt][nt][3] -= as1 * ce1.y;
            }
        }
#pragma unroll
        for (int mt = 0; mt < 2; mt++) {
            float sA = 0.f, sB = 0.f;
#pragma unroll
            for (int nt = 0; nt < 8; nt++) {
                sA += agg[mt][nt][0] * agg[mt][nt][0] + agg[mt][nt][1] * agg[mt][nt][1];
                sB += agg[mt][nt][2] * agg[mt][nt][2] + agg[mt][nt][3] * agg[mt][nt][3];
            }
            sA += __shfl_xor_sync(0xffffffffu, sA, 1);
            sA += __shfl_xor_sync(0xffffffffu, sA, 2);
            sB += __shfl_xor_sync(0xffffffffu, sB, 1);
            sB += __shfl_xor_sync(0xffffffffu, sB, 2);
            if (qc == 0) {
                int kA = kg * 32 + mt * 16 + qr;
                smf[(SM_RED >> 2) + kA * 5 + cg] = sA;
                smf[(SM_RED >> 2) + (kA + 8) * 5 + cg] = sB;
            }
        }
    }
    __syncthreads();
    if (t < 64) {
        float ss = 0.f;
#pragma unroll
        for (int i = 0; i < 4; i++) ss += smf[(SM_RED >> 2) + t * 5 + i];
        float dk = fmaxf(sqrtf(ss), 1e-12f);
        smf[(SM_RK >> 2) + t] = 1.0f / dk;
        float gp = ss / (dk * dk);
        gp += __shfl_xor_sync(0xffffffffu, gp, 16);
        gp += __shfl_xor_sync(0xffffffffu, gp, 8);
        gp += __shfl_xor_sync(0xffffffffu, gp, 4);
        gp += __shfl_xor_sync(0xffffffffu, gp, 2);
        gp += __shfl_xor_sync(0xffffffffu, gp, 1);
        if (lane == 0) smf[(SM_G2 >> 2) + wp] = gp;
    }
    __syncthreads();
    if (wp >= 8) {
        const float rg = 1.0f / fmaxf(sqrtf(smf[SM_G2 >> 2] + smf[(SM_G2 >> 2) + 1]), 1e-12f);
        float* on = out + (size_t)n * KK * CD;
#pragma unroll
        for (int mt = 0; mt < 2; mt++) {
            int kA = kg * 32 + mt * 16 + qr, kB = kA + 8;
            float r0 = smf[(SM_RK >> 2) + kA] * rg;
            float r1 = smf[(SM_RK >> 2) + kB] * rg;
#pragma unroll
            for (int nt = 0; nt < 8; nt++) {
                int c0 = cg * 64 + nt * 8 + qc * 2;
                *(float2*)(on + kA * CD + c0) =
                    make_float2(agg[mt][nt][0] * r0, agg[mt][nt][1] * r0);
                *(float2*)(on + kB * CD + c0) =
                    make_float2(agg[mt][nt][2] * r1, agg[mt][nt][3] * r1);
            }
        }
    }
}

// ------------------------------------------------------------------------------
extern "C" void kernel_launch(void* const* d_in, const int* in_sizes, int n_in,
                              void* d_out, int out_size) {
    const float* x    = (const float*)d_in[0];  // (128, 256, 32, 32)
    const float* w    = (const float*)d_in[1];  // (64, 256)
    const float* b    = (const float*)d_in[2];  // (64)
    const float* cent = (const float*)d_in[3];  // (64, 256)
    float* out = (float*)d_out;                 // (128, 16384)

    cudaFuncSetAttribute(netvlad_mma, cudaFuncAttributeMaxDynamicSharedMemorySize, SM_TOTAL);
    netvlad_mma<<<NB, 512, SM_TOTAL>>>(x, w, b, cent, out);
}